// round 8
// baseline (speedup 1.0000x reference)
#include <cuda_runtime.h>

// ShapeNet1D hat-basis evaluation — row-aligned vectorized streaming stores,
// compile-time-stride specialization.
//
// Reference telescopes to out[p][k] = T(k-1) - T(k), T(-1)=1, T(n_el)=0,
//   T(j) = relu(1 - relu(x_full[j+1]-x)/(h_j+1e-9))
//        = clamp01((x - x_j + eps) * inv_j)             (exact rewrite)
// Sentinel-shifted node table tc[c], c in [0, n_cols]:
//   tc[0]            -> T == 1   (left sentinel)
//   tc[c], 1<=c<n_cols: inv = 1/(x_full[c]-x_full[c-1]+eps),
//                       coef = (eps - x_full[c-1])*inv,  T = sat(x*inv+coef)
//   tc[c>=n_cols]    -> T == 0   (right sentinel)
//   out[p][k] = tc[k] - tc[k+1]
//
// Layout: thread t owns 4 consecutive columns, shifted per row by
// s = (4 - p%4)%4 so (p*n_cols + s + 4t) % 4 == 0 -> every quad store is a
// 16B-aligned STG.128 (full-sector write streams). Thread t register-caches
// tc[4t..4t+8], covering all 4 shifts with compile-time indices.
// __stcs: output is write-once/never-read, don't churn L2.
//
// R8: NCOLS=2049 compile-time specialization (row offsets become STG
// immediates -> fewer live address regs), __launch_bounds__(512,3) for
// 3 blocks/SM, single-wave grid (432 blocks <= 444 resident).

struct Coef { float inv, c; };

__device__ __forceinline__ float Tof(float x, Coef k) {
    return __saturatef(fmaf(x, k.inv, k.c));
}

template<int S, int NCOLS>
__device__ __forceinline__
void do_row(float x, const Coef (&rc)[9], float* __restrict__ orow,
            int c0base, int t)
{
    const int c0 = S + c0base;          // first column of this thread's quad
    const float U0 = Tof(x, rc[S + 0]);
    const float U1 = Tof(x, rc[S + 1]);
    const float U2 = Tof(x, rc[S + 2]);
    const float U3 = Tof(x, rc[S + 3]);
    const float U4 = Tof(x, rc[S + 4]);

    if (c0 + 3 < NCOLS) {
        // (row_base + c0) % 4 == 0 by construction -> aligned STG.128
        const float4 v = make_float4(U0 - U1, U1 - U2, U2 - U3, U3 - U4);
        __stcs(reinterpret_cast<float4*>(orow + c0), v);
    } else {
        if (c0     < NCOLS) __stcs(orow + c0,     U0 - U1);
        if (c0 + 1 < NCOLS) __stcs(orow + c0 + 1, U1 - U2);
        if (c0 + 2 < NCOLS) __stcs(orow + c0 + 2, U2 - U3);
    }
    // single leftover column just past this thread's quad.
    // c0+4 == NCOLS-1 has an integer-thread solution only for S=0 (t=511),
    // so no column is ever double-stored across shifts.
    if (c0 + 4 == NCOLS - 1) {
        __stcs(orow + c0 + 4, U4 - Tof(x, rc[S + 5]));   // S+5 <= 8
    }
    // head columns [0, S) of the row (thread 0 only)
    if (S > 0 && t == 0) {
        #pragma unroll
        for (int j = 0; j < S; ++j)
            __stcs(orow + j, Tof(x, rc[j]) - Tof(x, rc[j + 1]));
    }
}

template<int NCOLS>
__device__ __forceinline__
void load_coefs(Coef (&rc)[9], const float* __restrict__ x_full, int c0b)
{
    #pragma unroll
    for (int j = 0; j < 9; ++j) {
        const int c = c0b + j;
        if (c == 0)          { rc[j].inv = 0.0f; rc[j].c = 1.0f; }   // T=1
        else if (c >= NCOLS) { rc[j].inv = 0.0f; rc[j].c = 0.0f; }   // T=0
        else {
            const float xa  = __ldg(&x_full[c - 1]);
            const float xb  = __ldg(&x_full[c]);
            const float inv = 1.0f / ((xb - xa) + 1e-9f);
            rc[j].inv = inv;
            rc[j].c   = (1e-9f - xa) * inv;
        }
    }
}

template<int NCOLS>
__global__ __launch_bounds__(512, 3)
void hat_rows_fixed(const float* __restrict__ x_eval,
                    const float* __restrict__ x_full,
                    float* __restrict__ out,
                    int n_points, int rows_per_block)
{
    const int t = threadIdx.x;
    const int c0b = 4 * t;

    Coef rc[9];
    load_coefs<NCOLS>(rc, x_full, c0b);

    const int p0 = blockIdx.x * rows_per_block;     // multiple of 4
    const int p1 = min(p0 + rows_per_block, n_points);

    int p = p0;
    // 4 rows per iteration: shift pattern for rows p0+0..3 is s = 0,3,2,1.
    // NCOLS is compile-time -> row offsets fold into STG immediates.
    for (; p + 4 <= p1; p += 4) {
        const float4 xs = *reinterpret_cast<const float4*>(x_eval + p);
        float* o = out + (unsigned)p * (unsigned)NCOLS;
        do_row<0, NCOLS>(xs.x, rc, o,             c0b, t);
        do_row<3, NCOLS>(xs.y, rc, o + NCOLS,     c0b, t);
        do_row<2, NCOLS>(xs.z, rc, o + 2 * NCOLS, c0b, t);
        do_row<1, NCOLS>(xs.w, rc, o + 3 * NCOLS, c0b, t);
    }
    for (; p < p1; ++p) {   // tail rows (not hit for n_points=32768)
        const float x = __ldg(&x_eval[p]);
        float* o = out + (unsigned)p * (unsigned)NCOLS;
        switch ((4 - (p & 3)) & 3) {
            case 0:  do_row<0, NCOLS>(x, rc, o, c0b, t); break;
            case 1:  do_row<1, NCOLS>(x, rc, o, c0b, t); break;
            case 2:  do_row<2, NCOLS>(x, rc, o, c0b, t); break;
            default: do_row<3, NCOLS>(x, rc, o, c0b, t); break;
        }
    }
}

// ---- generic fallback (runtime n_cols; simple column-stationary form) ----
__global__ __launch_bounds__(256)
void hat_generic(const float* __restrict__ x_eval,
                 const float* __restrict__ x_full,
                 float* __restrict__ out,
                 int n_points, int n_cols)
{
    const int k = blockIdx.x * blockDim.x + threadIdx.x;
    if (k >= n_cols) return;
    float invL = 0.0f, cL = 2.0f;
    if (k > 0) {
        const float xa = __ldg(&x_full[k - 1]);
        const float xb = __ldg(&x_full[k]);
        invL = 1.0f / ((xb - xa) + 1e-9f);
        cL   = (1e-9f - xa) * invL;
    }
    float invRn = 0.0f, dR = 2.0f;
    if (k < n_cols - 1) {
        const float xa = __ldg(&x_full[k]);
        const float xb = __ldg(&x_full[k + 1]);
        const float invR = 1.0f / ((xb - xa) + 1e-9f);
        invRn = -invR;
        dR    = xb * invR;
    }
    for (int p = 0; p < n_points; ++p) {
        const float x = __ldg(&x_eval[p]);
        out[(unsigned)p * (unsigned)n_cols + (unsigned)k] =
            __saturatef(fminf(fmaf(x, invL, cL), fmaf(x, invRn, dR)));
    }
}

extern "C" void kernel_launch(void* const* d_in, const int* in_sizes, int n_in,
                              void* d_out, int out_size)
{
    const float* x_eval = (const float*)d_in[0];   // [n_points] ([n_points,1] flat)
    const float* x_full = (const float*)d_in[1];   // [n_elements + 1]
    float* out = (float*)d_out;                    // [n_points, n_nodes] row-major

    const int n_points = in_sizes[0];              // 32768
    const int n_cols   = in_sizes[1];              // 2049 (= n_nodes)

    if (n_cols == 2049) {
        // single wave: 148 SMs x 3 blocks = 444 resident; 432 blocks launched
        int rows_per_block = 76;                   // multiple of 4
        const int grid = (n_points + rows_per_block - 1) / rows_per_block; // 432
        hat_rows_fixed<2049><<<grid, 512>>>(x_eval, x_full, out,
                                            n_points, rows_per_block);
    } else {
        const int threads = 256;
        const int grid = (n_cols + threads - 1) / threads;
        hat_generic<<<grid, threads>>>(x_eval, x_full, out, n_points, n_cols);
    }
}

// round 9
// speedup vs baseline: 1.0864x; 1.0864x over previous
#include <cuda_runtime.h>

// ShapeNet1D hat-basis evaluation — row-aligned vectorized streaming stores,
// compile-time-stride specialization, fine-grained blocks + x_eval prefetch.
//
// Reference telescopes to out[p][k] = T(k-1) - T(k), T(-1)=1, T(n_el)=0,
//   T(j) = relu(1 - relu(x_full[j+1]-x)/(h_j+1e-9))
//        = clamp01((x - x_j + eps) * inv_j)             (exact rewrite)
// Sentinel-shifted node table tc[c], c in [0, n_cols]:
//   tc[0]            -> T == 1   (left sentinel)
//   tc[c], 1<=c<n_cols: inv = 1/(x_full[c]-x_full[c-1]+eps),
//                       coef = (eps - x_full[c-1])*inv,  T = sat(x*inv+coef)
//   tc[c>=n_cols]    -> T == 0   (right sentinel)
//   out[p][k] = tc[k] - tc[k+1]
//
// Layout: thread t owns 4 consecutive columns, shifted per row by
// s = (4 - p%4)%4 so (p*n_cols + s + 4t) % 4 == 0 -> every quad store is a
// 16B-aligned STG.128 (full-sector write streams). Thread t register-caches
// tc[4t..4t+8], covering all 4 shifts with compile-time indices.
// __stcs: output is write-once/never-read, don't churn L2.
//
// R9: 1024 blocks x 32 rows (fine-grained work-stealing balance; R8 showed
// a rigid 3-blocks/SM single wave costs ~4% from 228-vs-221 row imbalance),
// plus software prefetch of the next x_eval float4 before current stores.

struct Coef { float inv, c; };

__device__ __forceinline__ float Tof(float x, Coef k) {
    return __saturatef(fmaf(x, k.inv, k.c));
}

template<int S, int NCOLS>
__device__ __forceinline__
void do_row(float x, const Coef (&rc)[9], float* __restrict__ orow,
            int c0base, int t)
{
    const int c0 = S + c0base;          // first column of this thread's quad
    const float U0 = Tof(x, rc[S + 0]);
    const float U1 = Tof(x, rc[S + 1]);
    const float U2 = Tof(x, rc[S + 2]);
    const float U3 = Tof(x, rc[S + 3]);
    const float U4 = Tof(x, rc[S + 4]);

    if (c0 + 3 < NCOLS) {
        // (row_base + c0) % 4 == 0 by construction -> aligned STG.128
        const float4 v = make_float4(U0 - U1, U1 - U2, U2 - U3, U3 - U4);
        __stcs(reinterpret_cast<float4*>(orow + c0), v);
    } else {
        if (c0     < NCOLS) __stcs(orow + c0,     U0 - U1);
        if (c0 + 1 < NCOLS) __stcs(orow + c0 + 1, U1 - U2);
        if (c0 + 2 < NCOLS) __stcs(orow + c0 + 2, U2 - U3);
    }
    // single leftover column just past this thread's quad.
    // c0+4 == NCOLS-1 has an integer-thread solution only for S=0 (t=511),
    // so no column is ever double-stored across shifts.
    if (c0 + 4 == NCOLS - 1) {
        __stcs(orow + c0 + 4, U4 - Tof(x, rc[S + 5]));   // S+5 <= 8
    }
    // head columns [0, S) of the row (thread 0 only)
    if (S > 0 && t == 0) {
        #pragma unroll
        for (int j = 0; j < S; ++j)
            __stcs(orow + j, Tof(x, rc[j]) - Tof(x, rc[j + 1]));
    }
}

template<int NCOLS>
__device__ __forceinline__
void load_coefs(Coef (&rc)[9], const float* __restrict__ x_full, int c0b)
{
    #pragma unroll
    for (int j = 0; j < 9; ++j) {
        const int c = c0b + j;
        if (c == 0)          { rc[j].inv = 0.0f; rc[j].c = 1.0f; }   // T=1
        else if (c >= NCOLS) { rc[j].inv = 0.0f; rc[j].c = 0.0f; }   // T=0
        else {
            const float xa  = __ldg(&x_full[c - 1]);
            const float xb  = __ldg(&x_full[c]);
            const float inv = 1.0f / ((xb - xa) + 1e-9f);
            rc[j].inv = inv;
            rc[j].c   = (1e-9f - xa) * inv;
        }
    }
}

template<int NCOLS>
__global__ __launch_bounds__(512)
void hat_rows_fixed(const float* __restrict__ x_eval,
                    const float* __restrict__ x_full,
                    float* __restrict__ out,
                    int n_points, int rows_per_block)
{
    const int t = threadIdx.x;
    const int c0b = 4 * t;

    Coef rc[9];
    load_coefs<NCOLS>(rc, x_full, c0b);

    const int p0 = blockIdx.x * rows_per_block;     // multiple of 4
    const int p1 = min(p0 + rows_per_block, n_points);

    int p = p0;
    if (p + 4 <= p1) {
        // prefetch the first row-quad's x values
        float4 xs = *reinterpret_cast<const float4*>(x_eval + p);
        for (; p + 4 <= p1; p += 4) {
            const float4 cur = xs;
            // prefetch next quad before this quad's stores occupy the LSU
            if (p + 8 <= p1)
                xs = *reinterpret_cast<const float4*>(x_eval + p + 4);
            float* o = out + (unsigned)p * (unsigned)NCOLS;
            // shift pattern for rows p+0..3 is s = 0,3,2,1 (p multiple of 4)
            do_row<0, NCOLS>(cur.x, rc, o,             c0b, t);
            do_row<3, NCOLS>(cur.y, rc, o + NCOLS,     c0b, t);
            do_row<2, NCOLS>(cur.z, rc, o + 2 * NCOLS, c0b, t);
            do_row<1, NCOLS>(cur.w, rc, o + 3 * NCOLS, c0b, t);
        }
    }
    for (; p < p1; ++p) {   // tail rows (not hit for n_points=32768)
        const float x = __ldg(&x_eval[p]);
        float* o = out + (unsigned)p * (unsigned)NCOLS;
        switch ((4 - (p & 3)) & 3) {
            case 0:  do_row<0, NCOLS>(x, rc, o, c0b, t); break;
            case 1:  do_row<1, NCOLS>(x, rc, o, c0b, t); break;
            case 2:  do_row<2, NCOLS>(x, rc, o, c0b, t); break;
            default: do_row<3, NCOLS>(x, rc, o, c0b, t); break;
        }
    }
}

// ---- generic fallback (runtime n_cols; simple column-stationary form) ----
__global__ __launch_bounds__(256)
void hat_generic(const float* __restrict__ x_eval,
                 const float* __restrict__ x_full,
                 float* __restrict__ out,
                 int n_points, int n_cols)
{
    const int k = blockIdx.x * blockDim.x + threadIdx.x;
    if (k >= n_cols) return;
    float invL = 0.0f, cL = 2.0f;
    if (k > 0) {
        const float xa = __ldg(&x_full[k - 1]);
        const float xb = __ldg(&x_full[k]);
        invL = 1.0f / ((xb - xa) + 1e-9f);
        cL   = (1e-9f - xa) * invL;
    }
    float invRn = 0.0f, dR = 2.0f;
    if (k < n_cols - 1) {
        const float xa = __ldg(&x_full[k]);
        const float xb = __ldg(&x_full[k + 1]);
        const float invR = 1.0f / ((xb - xa) + 1e-9f);
        invRn = -invR;
        dR    = xb * invR;
    }
    for (int p = 0; p < n_points; ++p) {
        const float x = __ldg(&x_eval[p]);
        out[(unsigned)p * (unsigned)n_cols + (unsigned)k] =
            __saturatef(fminf(fmaf(x, invL, cL), fmaf(x, invRn, dR)));
    }
}

extern "C" void kernel_launch(void* const* d_in, const int* in_sizes, int n_in,
                              void* d_out, int out_size)
{
    const float* x_eval = (const float*)d_in[0];   // [n_points] ([n_points,1] flat)
    const float* x_full = (const float*)d_in[1];   // [n_elements + 1]
    float* out = (float*)d_out;                    // [n_points, n_nodes] row-major

    const int n_points = in_sizes[0];              // 32768
    const int n_cols   = in_sizes[1];              // 2049 (= n_nodes)

    if (n_cols == 2049) {
        // fine-grained blocks: 1024 x 32 rows -> work-stealing balance,
        // 32-row tail quantization, ~2.3 streamed waves at 3 blocks/SM
        const int rows_per_block = 32;             // multiple of 4
        const int grid = (n_points + rows_per_block - 1) / rows_per_block; // 1024
        hat_rows_fixed<2049><<<grid, 512>>>(x_eval, x_full, out,
                                            n_points, rows_per_block);
    } else {
        const int threads = 256;
        const int grid = (n_cols + threads - 1) / threads;
        hat_generic<<<grid, threads>>>(x_eval, x_full, out, n_points, n_cols);
    }
}